// round 1
// baseline (speedup 1.0000x reference)
#include <cuda_runtime.h>

// Problem constants
#define T_LEN   2048
#define BATCH   64
#define IDIM    128
#define HDIM    128
#define FCDIM   32
#define ODIM    2
#define CHUNKS  32
#define TC      64          // timesteps per chunk (T_LEN / CHUNKS)
#define TB      32          // tt-block held in accumulator registers
#define NTHREADS 512

// Scratch (allocation-free rule: __device__ globals)
__device__ float g_Ascr[BATCH * CHUNKS * HDIM];   // chunk-local A = prod f
__device__ float g_Bscr[BATCH * CHUNKS * HDIM];   // chunk-local B
__device__ float g_olast[BATCH * HDIM];           // sigmoid(o) at t = T-1

// Packed fp32x2 FMA (Blackwell FFMA2 — 2x fp32 FMA throughput, PTX-only)
__device__ __forceinline__ unsigned long long ffma2(unsigned long long a,
                                                    unsigned long long b,
                                                    unsigned long long c) {
    unsigned long long d;
    asm("fma.rn.f32x2 %0, %1, %2, %3;" : "=l"(d) : "l"(a), "l"(b), "l"(c));
    return d;
}

__device__ __forceinline__ float lo_plus_hi(unsigned long long v) {
    float2 f = *reinterpret_cast<float2*>(&v);
    return f.x + f.y;
}

__device__ __forceinline__ float fast_sigmoid(float x) {
    return 1.0f / (1.0f + __expf(-x));
}

// ---------------------------------------------------------------------------
// Kernel 1: per-(batch, chunk) gate GEMM + chunk-local affine scan reduction.
// grid = (CHUNKS, BATCH), block = 512. Thread (gate, h) = (tid>>7, tid&127).
// Each thread computes preact[gate][t0..t0+63][h] via a register-tiled dot
// against the shared x tile, writes preacts to smem, then 128 threads do the
// 64-step affine reduction (A, B) for this chunk.
// ---------------------------------------------------------------------------
__global__ void __launch_bounds__(NTHREADS, 1)
gates_kernel(const float* __restrict__ x,
             const float* __restrict__ wg, const float* __restrict__ wi,
             const float* __restrict__ wf, const float* __restrict__ wo,
             const float* __restrict__ bg, const float* __restrict__ bi,
             const float* __restrict__ bf, const float* __restrict__ bo)
{
    extern __shared__ float smem[];
    float* xs  = smem;                  // [TC][IDIM]   = 32 KB
    float* gsm = smem + TC * IDIM;      // [4][TC][HDIM] = 128 KB

    const int b   = blockIdx.y;
    const int ch  = blockIdx.x;
    const int tid = threadIdx.x;
    const int t0  = ch * TC;

    // Load x tile (coalesced float4): x[t0+tt, b, :] for tt in [0,TC)
    for (int idx = tid; idx < TC * IDIM / 4; idx += NTHREADS) {
        const int tt = idx >> 5;        // idx / (IDIM/4)
        const int i4 = idx & 31;
        float4 v = *(const float4*)(x + (size_t)(t0 + tt) * (BATCH * IDIM)
                                      + (size_t)b * IDIM + i4 * 4);
        *(float4*)(xs + tt * IDIM + i4 * 4) = v;
    }
    __syncthreads();

    const int gate = tid >> 7;
    const int h    = tid & 127;
    const float* wsel = (gate == 0) ? wg : (gate == 1) ? wi : (gate == 2) ? wf : wo;
    const float* wrow = wsel + ((size_t)b * HDIM + h) * IDIM;

    for (int tb = 0; tb < TC; tb += TB) {
        unsigned long long acc[TB];
        #pragma unroll
        for (int j = 0; j < TB; j++) acc[j] = 0ull;

        #pragma unroll 1                 // keep body within L0 I-cache
        for (int k0 = 0; k0 < IDIM; k0 += 8) {
            // 8 weights for this thread's row, packed as 4 x f32x2
            ulonglong2 wa = *(const ulonglong2*)(wrow + k0);
            ulonglong2 wb = *(const ulonglong2*)(wrow + k0 + 4);
            #pragma unroll
            for (int j = 0; j < TB; j++) {
                const ulonglong2* xp =
                    (const ulonglong2*)(xs + (tb + j) * IDIM + k0);
                ulonglong2 x0 = xp[0];   // x[k0..k0+3]   (LDS.128, warp-broadcast)
                ulonglong2 x1 = xp[1];   // x[k0+4..k0+7]
                acc[j] = ffma2(wa.x, x0.x, acc[j]);
                acc[j] = ffma2(wa.y, x0.y, acc[j]);
                acc[j] = ffma2(wb.x, x1.x, acc[j]);
                acc[j] = ffma2(wb.y, x1.y, acc[j]);
            }
        }

        #pragma unroll
        for (int j = 0; j < TB; j++)
            gsm[gate * (TC * HDIM) + (tb + j) * HDIM + h] = lo_plus_hi(acc[j]);
    }
    __syncthreads();

    // Chunk-local affine scan: c_out = A*c_in + B, iterated t ascending.
    if (tid < HDIM) {
        const int hh  = tid;
        const float bgv = bg[b * HDIM + hh];
        const float biv = bi[b * HDIM + hh];
        const float bfv = bf[b * HDIM + hh];
        float A = 1.0f, Bc = 0.0f;
        #pragma unroll 4
        for (int tt = 0; tt < TC; tt++) {
            const float gv = tanhf(gsm[0 * (TC * HDIM) + tt * HDIM + hh] + bgv);
            const float iv = fast_sigmoid(gsm[1 * (TC * HDIM) + tt * HDIM + hh] + biv);
            const float fv = fast_sigmoid(gsm[2 * (TC * HDIM) + tt * HDIM + hh] + bfv);
            Bc = fv * Bc + iv * gv;
            A *= fv;
        }
        g_Ascr[(b * CHUNKS + ch) * HDIM + hh] = A;
        g_Bscr[(b * CHUNKS + ch) * HDIM + hh] = Bc;
        if (ch == CHUNKS - 1) {
            const float ov = fast_sigmoid(
                gsm[3 * (TC * HDIM) + (TC - 1) * HDIM + hh] + bo[b * HDIM + hh]);
            g_olast[b * HDIM + hh] = ov;
        }
    }
}

// ---------------------------------------------------------------------------
// Kernel 2: compose the 32 chunk-affines per (b,h), then the classifier head.
// grid = BATCH, block = HDIM.
// ---------------------------------------------------------------------------
__global__ void final_kernel(const float* __restrict__ fc1w, const float* __restrict__ fc1b,
                             const float* __restrict__ fc2w, const float* __restrict__ fc2b,
                             float* __restrict__ out)
{
    __shared__ float hs[HDIM];
    __shared__ float zs[FCDIM];
    __shared__ float z2[ODIM];

    const int b = blockIdx.x;
    const int h = threadIdx.x;

    float c = 0.0f;
    #pragma unroll 1
    for (int ch = 0; ch < CHUNKS; ch++) {
        const int idx = (b * CHUNKS + ch) * HDIM + h;
        c = g_Ascr[idx] * c + g_Bscr[idx];
    }
    hs[h] = g_olast[b * HDIM + h] * tanhf(c);
    __syncthreads();

    if (h < FCDIM) {
        float z = fc1b[h];
        #pragma unroll 8
        for (int k = 0; k < HDIM; k++) z += fc1w[h * HDIM + k] * hs[k];
        zs[h] = tanhf(z);
    }
    __syncthreads();

    if (h < ODIM) {
        float z = fc2b[h];
        #pragma unroll
        for (int k = 0; k < FCDIM; k++) z += fc2w[h * FCDIM + k] * zs[k];
        z2[h] = z;
    }
    __syncthreads();

    if (h == 0) {
        const float m   = fmaxf(z2[0], z2[1]);
        const float lse = m + logf(expf(z2[0] - m) + expf(z2[1] - m));
        out[b * ODIM + 0] = z2[0] - lse;
        out[b * ODIM + 1] = z2[1] - lse;
    }
}

// ---------------------------------------------------------------------------
extern "C" void kernel_launch(void* const* d_in, const int* in_sizes, int n_in,
                              void* d_out, int out_size)
{
    const float* x   = (const float*)d_in[0];
    const float* wg  = (const float*)d_in[1];
    const float* wi  = (const float*)d_in[2];
    const float* wf  = (const float*)d_in[3];
    const float* wo  = (const float*)d_in[4];
    // d_in[5..8] = w_hg/w_hi/w_hf/w_ho: multiply a zero hidden state -> unused.
    const float* bg  = (const float*)d_in[9];
    const float* bi  = (const float*)d_in[10];
    const float* bf  = (const float*)d_in[11];
    const float* bo  = (const float*)d_in[12];
    const float* f1w = (const float*)d_in[13];
    const float* f1b = (const float*)d_in[14];
    const float* f2w = (const float*)d_in[15];
    const float* f2b = (const float*)d_in[16];

    const int smem_bytes = (TC * IDIM + 4 * TC * HDIM) * (int)sizeof(float); // 160 KB
    cudaFuncSetAttribute(gates_kernel,
                         cudaFuncAttributeMaxDynamicSharedMemorySize, smem_bytes);

    gates_kernel<<<dim3(CHUNKS, BATCH), NTHREADS, smem_bytes>>>(
        x, wg, wi, wf, wo, bg, bi, bf, bo);
    final_kernel<<<BATCH, HDIM>>>(f1w, f1b, f2w, f2b, (float*)d_out);
}